// round 13
// baseline (speedup 1.0000x reference)
#include <cuda_runtime.h>
#include <cstdint>

// ---------------- problem constants ----------------
#define NPOS   8192          // 64 x 128 spatial positions (x1|x2 concat)
#define NCH    64
#define KC     8
#define TQ     64            // kv chunk length staged in smem (double-buffered)
#define ATT_SCALE 0.35355339059327373f   // 8^-0.5

// ---------------- scratch (device globals; no allocations) ----------------
__device__ float g_Q[4 * KC * NPOS];        // [stage][k][blocked-pos]
__device__ float g_K[4 * KC * NPOS];
__device__ float g_V[4 * NCH * NPOS];       // [stage][c][blocked-pos]
__device__ float g_ctx[4 * NCH * NPOS];     // context, blocked layout
__device__ float g_pacc0[32 * NCH * NPOS];  // stage-0 split partial acc
__device__ float g_pacc1[8 * NCH * NPOS];   // stage-1 split partial acc
__device__ float g_pl0[32 * NPOS];          // stage-0 split partial l
__device__ float g_pl1[8 * NPOS];           // stage-1 split partial l

// ---------------- packed f32x2 helpers ----------------
typedef unsigned long long u64;

__device__ __forceinline__ u64 pack2(float lo, float hi) {
    u64 r;
    asm("mov.b64 %0, {%1, %2};" : "=l"(r) : "f"(lo), "f"(hi));
    return r;
}
__device__ __forceinline__ void unpack2(u64 v, float& lo, float& hi) {
    asm("mov.b64 {%0, %1}, %2;" : "=f"(lo), "=f"(hi) : "l"(v));
}
__device__ __forceinline__ u64 fma2(u64 a, u64 b, u64 c) {
    u64 d;
    asm("fma.rn.f32x2 %0, %1, %2, %3;" : "=l"(d) : "l"(a), "l"(b), "l"(c));
    return d;
}
__device__ __forceinline__ u64 mul2(u64 a, u64 b) {
    u64 d;
    asm("mul.rn.f32x2 %0, %1, %2;" : "=l"(d) : "l"(a), "l"(b));
    return d;
}

// ---------------- cp.async helpers ----------------
__device__ __forceinline__ void cpasync4(uint32_t dst, const float* src) {
    asm volatile("cp.async.ca.shared.global [%0], [%1], 4;" :: "r"(dst), "l"(src));
}
#define CP_COMMIT() asm volatile("cp.async.commit_group;" ::: "memory")
#define CP_WAIT0()  asm volatile("cp.async.wait_group 0;"  ::: "memory")

// Blocked index: stage s (scale = 2^s), flat pos (h*128 + wfull) ->
// block * Pb + p, matching the reference's to_blocks() permutation.
__device__ __forceinline__ int blocked_idx(int s, int pos) {
    int h    = pos >> 7;
    int wf   = pos & 127;
    int half = wf >> 6;
    int w    = wf & 63;
    int l2hl = 6 - s;                 // log2(block edge)
    int msk  = (1 << l2hl) - 1;
    int bi = h >> l2hl, r = h & msk;
    int bj = w >> l2hl, c = w & msk;
    int block = (bi << s) + bj;
    int p  = (((r << l2hl) + c) << 1) + half;
    int Pb = 1 << (2 * l2hl + 1);     // hl*wl*2
    return block * Pb + p;
}

// ================= kernel 1: QKV projections (BN folded), blocked layout ===
__global__ void __launch_bounds__(256) qkv_kernel(
    const float* __restrict__ x1, const float* __restrict__ x2,
    const float* __restrict__ Wq, const float* __restrict__ bq,
    const float* __restrict__ gq, const float* __restrict__ betq,
    const float* __restrict__ Wk, const float* __restrict__ bk,
    const float* __restrict__ gk, const float* __restrict__ betk,
    const float* __restrict__ Wv, const float* __restrict__ bv)
{
    __shared__ float w_s[80 * 64];   // 8 q + 8 k + 64 v effective rows
    __shared__ float b_s[80];
    __shared__ float xs[64 * 64];    // [c][p]

    const int s   = blockIdx.y;      // stage (scale = 2^s)
    const int til = blockIdx.x;      // 0..127 position tiles of 64
    const int tid = threadIdx.x;

    for (int i = tid; i < 80 * 64; i += 256) {
        int r = i >> 6, c = i & 63;
        float w;
        if (r < 8)       w = gq[s * 8 + r] * Wq[(s * 8 + r) * 64 + c];
        else if (r < 16) w = gk[s * 8 + (r - 8)] * Wk[(s * 8 + (r - 8)) * 64 + c];
        else             w = Wv[(s * 64 + (r - 16)) * 64 + c];
        w_s[i] = w;
    }
    if (tid < 80) {
        int r = tid;
        float b;
        if (r < 8)       b = gq[s * 8 + r] * bq[s * 8 + r] + betq[s * 8 + r];
        else if (r < 16) b = gk[s * 8 + (r - 8)] * bk[s * 8 + (r - 8)] + betk[s * 8 + (r - 8)];
        else             b = bv[s * 64 + (r - 16)];
        b_s[r] = b;
    }
    const int pos0 = til * 64;
    for (int i = tid; i < 64 * 64; i += 256) {
        int c = i >> 6, p = i & 63;
        int pos = pos0 + p;
        int h = pos >> 7, wf = pos & 127;
        xs[c * 64 + p] = (wf < 64) ? x1[c * 4096 + h * 64 + wf]
                                   : x2[c * 4096 + h * 64 + (wf - 64)];
    }
    __syncthreads();

    const int p = tid & 63;
    const int g = tid >> 6;          // 4 thread groups, 20 rows each
    float acc[20];
    #pragma unroll
    for (int j = 0; j < 20; j++) acc[j] = b_s[g + 4 * j];

    for (int c = 0; c < 64; c++) {
        float xv = xs[c * 64 + p];
        #pragma unroll
        for (int j = 0; j < 20; j++)
            acc[j] += w_s[(g + 4 * j) * 64 + c] * xv;
    }

    const int bidx = blocked_idx(s, pos0 + p);
    #pragma unroll
    for (int j = 0; j < 20; j++) {
        int r = g + 4 * j;
        if (r < 8)       g_Q[(s * KC + r) * NPOS + bidx] = acc[j];
        else if (r < 16) g_K[(s * KC + (r - 8)) * NPOS + bidx] = acc[j];
        else             g_V[(s * NCH + (r - 16)) * NPOS + bidx] = acc[j];
    }
}

// ================= kernel 2: block attention ===============================
// 256 threads/CTA, 1 query/thread -> ~110 regs -> 2 CTAs/SM (16 warps/SM)
// for latency hiding. FMA2 pipe and LDS crossbar co-saturated by design.
// Long stage-2 CTAs first, short stage-3 last. Softmax with fixed shift 0
// (exact by invariance). KV chunks streamed with cp.async double buffering.

// Issue one chunk's K/V loads into smem buffer via cp.async (no commit).
// Layout per buffer: 18 quad-rows (2 K + 16 V) x TQ columns x 4 floats.
__device__ __forceinline__ void load_chunk(uint32_t buf_base,
                                           const float* __restrict__ Kb,
                                           const float* __restrict__ Vb,
                                           int c0, int tid)
{
    for (int i = tid; i < 18 * TQ; i += 256) {
        int row = i >> 6;                     // TQ = 64
        int q   = i & (TQ - 1);
        const float* src = (row < 2)
            ? (Kb + (4 * row) * NPOS + c0 + q)
            : (Vb + (4 * (row - 2)) * NPOS + c0 + q);
        uint32_t d = buf_base + i * 16;
        cpasync4(d,      src);
        cpasync4(d + 4,  src + NPOS);
        cpasync4(d + 8,  src + 2 * NPOS);
        cpasync4(d + 12, src + 3 * NPOS);
    }
}

__global__ void __launch_bounds__(256, 2) attn_kernel()
{
    __shared__ __align__(16) float KVf[2][18 * TQ * 4];   // 2 x 18KB

    const int bid = blockIdx.x;
    const int tid = threadIdx.x;

    int stage, bb, q0, split, kv0, nchunks, nq;
    if (bid < 32) {                           // stage 2 (long CTAs first): 16 blk x 2 qt
        stage = 2;
        bb = (bid >> 1) * 512; q0 = (bid & 1) * 256;
        split = 0; kv0 = 0; nchunks = 8; nq = 256;
    } else if (bid < 1056) {                  // stage 0: 32 qt x 32 kv-splits
        int i = bid - 32; stage = 0; bb = 0;
        q0 = (i >> 5) * 256;
        split = i & 31; kv0 = split * 256; nchunks = 4; nq = 256;
    } else if (bid < 1312) {                  // stage 1: 32 qt x 8 kv-splits
        int i = bid - 1056; stage = 1;
        int qt = i >> 3; split = i & 7;
        bb = (qt >> 3) * 2048; q0 = (qt & 7) * 256;
        kv0 = split * 256; nchunks = 4; nq = 256;
    } else {                                  // stage 3 (short CTAs last): 64 blocks
        int i = bid - 1312; stage = 3;
        bb = i * 128; q0 = 0;
        split = 0; kv0 = 0; nchunks = 2; nq = 128;
    }

    const bool active  = tid < nq;
    const bool wactive = (tid & ~31) < nq;    // warp-uniform compute guard
    const int qi = q0 + (active ? tid : 0);

    const float* Qp = g_Q + stage * KC * NPOS + bb;
    const float* Kb = g_K + stage * KC * NPOS + bb;
    const float* Vb = g_V + stage * NCH * NPOS + bb;

    const uint32_t smem0 = (uint32_t)__cvta_generic_to_shared(&KVf[0][0]);
    const uint32_t smem1 = (uint32_t)__cvta_generic_to_shared(&KVf[1][0]);

    u64 q2[4];
    #pragma unroll
    for (int j = 0; j < 4; j++)
        q2[j] = pack2(Qp[(2 * j) * NPOS + qi] * ATT_SCALE,
                      Qp[(2 * j + 1) * NPOS + qi] * ATT_SCALE);

    u64 acc2[32];
    #pragma unroll
    for (int j = 0; j < 32; j++) acc2[j] = 0ull;
    float l = 0.0f;

    // prologue: start chunk 0
    load_chunk(smem0, Kb, Vb, kv0, tid);
    CP_COMMIT();

    for (int ch = 0; ch < nchunks; ch++) {
        CP_WAIT0();
        __syncthreads();                       // buf[cur] ready; buf[cur^1] free
        const int cur = ch & 1;
        if (ch + 1 < nchunks) {
            load_chunk(cur ? smem0 : smem1, Kb, Vb, kv0 + (ch + 1) * TQ, tid);
            CP_COMMIT();
        }
        const ulonglong2* KB = (const ulonglong2*)&KVf[cur][0];

        if (wactive) {
            #pragma unroll 2
            for (int q = 0; q < TQ; q++) {
                ulonglong2 k01 = KB[q];
                ulonglong2 k23 = KB[TQ + q];
                u64 d = mul2(q2[0], k01.x);
                d = fma2(q2[1], k01.y, d);
                d = fma2(q2[2], k23.x, d);
                d = fma2(q2[3], k23.y, d);
                float a0, a1;
                unpack2(d, a0, a1);
                float e = __expf(a0 + a1);
                l += e;
                u64 e2 = pack2(e, e);
                #pragma unroll
                for (int jj = 0; jj < 16; jj++) {
                    ulonglong2 v = KB[(2 + jj) * TQ + q];
                    acc2[2 * jj]     = fma2(e2, v.x, acc2[2 * jj]);
                    acc2[2 * jj + 1] = fma2(e2, v.y, acc2[2 * jj + 1]);
                }
            }
        }
    }

    if (!active) return;

    if (stage <= 1) {                         // raw split partials
        float* pl = (stage == 0) ? g_pl0 : g_pl1;
        float* pa = (stage == 0) ? g_pacc0 : g_pacc1;
        pl[split * NPOS + bb + qi] = l;
        float* dst = pa + split * NCH * NPOS + bb + qi;
        #pragma unroll
        for (int j = 0; j < 32; j++) {
            float lo, hi;
            unpack2(acc2[j], lo, hi);
            dst[(2 * j) * NPOS] = lo;  dst[(2 * j + 1) * NPOS] = hi;
        }
    } else {                                  // finalize directly
        float inv = 1.0f / l;
        float* dst = g_ctx + stage * NCH * NPOS + bb + qi;
        #pragma unroll
        for (int j = 0; j < 32; j++) {
            float lo, hi;
            unpack2(acc2[j], lo, hi);
            dst[(2 * j) * NPOS] = lo * inv;  dst[(2 * j + 1) * NPOS] = hi * inv;
        }
    }
}

// ================= kernel 3: split merge (stages 0 and 1) ==================
// 128 CTAs x 256 threads: each thread merges 8 channels of one q4-group.
__global__ void __launch_bounds__(256) merge_kernel()
{
    int t = blockIdx.x * 256 + threadIdx.x;   // 0..32767
    int r  = t & 16383;
    int q4 = (r >> 3) * 4;                    // 2048 q-groups per stage
    int cg = (r & 7) * 8;                     // 8-channel group base
    if (t < 16384) {                          // stage 0: 32 splits
        float4 d = make_float4(0.f, 0.f, 0.f, 0.f);
        #pragma unroll
        for (int i = 0; i < 32; i++) {
            float4 l = *(const float4*)(g_pl0 + i * NPOS + q4);
            d.x += l.x; d.y += l.y; d.z += l.z; d.w += l.w;
        }
        float4 inv = make_float4(1.f / d.x, 1.f / d.y, 1.f / d.z, 1.f / d.w);
        #pragma unroll 2
        for (int cc = 0; cc < 8; cc++) {
            int c = cg + cc;
            float4 v = make_float4(0.f, 0.f, 0.f, 0.f);
            #pragma unroll
            for (int i = 0; i < 32; i++) {
                float4 a = *(const float4*)(g_pacc0 + (i * NCH + c) * NPOS + q4);
                v.x += a.x; v.y += a.y; v.z += a.z; v.w += a.w;
            }
            v.x *= inv.x; v.y *= inv.y; v.z *= inv.z; v.w *= inv.w;
            *(float4*)(g_ctx + c * NPOS + q4) = v;
        }
    } else {                                  // stage 1: 8 splits
        float4 d = make_float4(0.f, 0.f, 0.f, 0.f);
        #pragma unroll
        for (int i = 0; i < 8; i++) {
            float4 l = *(const float4*)(g_pl1 + i * NPOS + q4);
            d.x += l.x; d.y += l.y; d.z += l.z; d.w += l.w;
        }
        float4 inv = make_float4(1.f / d.x, 1.f / d.y, 1.f / d.z, 1.f / d.w);
        #pragma unroll 2
        for (int cc = 0; cc < 8; cc++) {
            int c = cg + cc;
            float4 v = make_float4(0.f, 0.f, 0.f, 0.f);
            #pragma unroll
            for (int i = 0; i < 8; i++) {
                float4 a = *(const float4*)(g_pacc1 + (i * NCH + c) * NPOS + q4);
                v.x += a.x; v.y += a.y; v.z += a.z; v.w += a.w;
            }
            v.x *= inv.x; v.y *= inv.y; v.z *= inv.z; v.w *= inv.w;
            *(float4*)(g_ctx + NCH * NPOS + c * NPOS + q4) = v;
        }
    }
}

// ================= kernel 4: final 1x1 conv (smem-tiled) ===================
// CTA = one image row h (128 positions) x one 32-channel output half.
// Per stage: stage ctx tile [64 d][128 wf] and Wo pair-slice in smem, then
// each thread computes 4 positions x 4 output channels with FFMA2.
__global__ void __launch_bounds__(256) final_kernel(
    const float* __restrict__ Wo, float* __restrict__ out)
{
    __shared__ __align__(16) float ctx_s[64 * 128];        // [d][wf] 32KB
    __shared__ __align__(16) float wo_s[16 * 65 * 2];      // [op][dd] u64, pad 65

    const int tid = threadIdx.x;
    const int h   = blockIdx.x;          // 0..63
    const int oh  = blockIdx.y;          // 0..1

    const int posq = tid >> 3;           // 0..31 -> 4 wf each
    const int och  = tid & 7;            // 0..7  -> 4 o each
    const int wf0  = posq * 4;

    u64 acc[4][2];
    #pragma unroll
    for (int p = 0; p < 4; p++) { acc[p][0] = 0ull; acc[p][1] = 0ull; }

    const int lwf = tid & 127;           // loop-invariant wf for tile fill
    const int ldd0 = tid >> 7;           // 0 or 1

    #pragma unroll
    for (int s = 0; s < 4; s++) {
        // ---- fill ctx tile (wf order); one blocked_idx per thread ----
        const float* cbase = g_ctx + s * NCH * NPOS + blocked_idx(s, h * 128 + lwf);
        #pragma unroll
        for (int k = 0; k < 32; k++) {
            int dd = ldd0 + 2 * k;
            ctx_s[dd * 128 + lwf] = cbase[dd * NPOS];
        }
        // ---- fill Wo pair slice: wo_s[op*130 + dd*2 + par] ----
        for (int i = tid; i < 2048; i += 256) {
            int op = i >> 7, rem = i & 127;
            int dd = rem >> 1, par = rem & 1;
            int o = oh * 32 + op * 2 + par;
            wo_s[op * 130 + dd * 2 + par] = Wo[o * 256 + s * 64 + dd];
        }
        __syncthreads();

        const u64* wo2 = (const u64*)wo_s;
        const int op0 = och * 2;
        #pragma unroll 8
        for (int dd = 0; dd < 64; dd++) {
            float4 cv = *(const float4*)(ctx_s + dd * 128 + wf0);
            u64 w0 = wo2[op0 * 65 + dd];
            u64 w1 = wo2[(op0 + 1) * 65 + dd];
            u64 c0 = pack2(cv.x, cv.x);
            u64 c1 = pack2(cv.y, cv.y);
            u64 c2 = pack2(cv.z, cv.z);
            u64 c3 = pack2(cv.w, cv.w);
            acc[0][0] = fma2(c0, w0, acc[0][0]);  acc[0][1] = fma2(c0, w1, acc[0][1]);
            acc[1][0] = fma2(c1, w0, acc[1][0]);  acc[1][1] = fma2(c1, w1, acc[1][1]);
            acc[2][0] = fma2(c2, w0, acc[2][0]);  acc[2][1] = fma2(c2, w1, acc[2][1]);
            acc[3][0] = fma2(c3, w0, acc[3][0]);  acc[3][1] = fma2(c3, w1, acc[3][1]);
        }
        __syncthreads();
    }

    // ---- write out: 4 o channels x 4 consecutive w positions ----
    const int halfimg = wf0 >> 6;        // uniform over the 4 positions
    const int w0i = wf0 & 63;
    float* ob = out + halfimg * 262144 + h * 64 + w0i;
    float vals[4][4];                    // [pos][o]
    #pragma unroll
    for (int p = 0; p < 4; p++) {
        unpack2(acc[p][0], vals[p][0], vals[p][1]);
        unpack2(acc[p][1], vals[p][2], vals[p][3]);
    }
    #pragma unroll
    for (int j = 0; j < 4; j++) {
        int o = oh * 32 + och * 4 + j;
        float4 v = make_float4(vals[0][j], vals[1][j], vals[2][j], vals[3][j]);
        *(float4*)(ob + o * 4096) = v;
    }
}

// ================= launch ==================================================
extern "C" void kernel_launch(void* const* d_in, const int* in_sizes, int n_in,
                              void* d_out, int out_size)
{
    const float* x1   = (const float*)d_in[0];
    const float* x2   = (const float*)d_in[1];
    const float* Wq   = (const float*)d_in[2];
    const float* bq   = (const float*)d_in[3];
    const float* gq   = (const float*)d_in[4];
    const float* betq = (const float*)d_in[5];
    const float* Wk   = (const float*)d_in[6];
    const float* bk   = (const float*)d_in[7];
    const float* gk   = (const float*)d_in[8];
    const float* betk = (const float*)d_in[9];
    const float* Wv   = (const float*)d_in[10];
    const float* bv   = (const float*)d_in[11];
    const float* Wo   = (const float*)d_in[12];
    float* out = (float*)d_out;

    qkv_kernel<<<dim3(128, 4), 256>>>(x1, x2, Wq, bq, gq, betq,
                                      Wk, bk, gk, betk, Wv, bv);
    attn_kernel<<<1376, 256>>>();
    merge_kernel<<<128, 256>>>();
    final_kernel<<<dim3(64, 2), 256>>>(Wo, out);
}

// round 17
// speedup vs baseline: 1.0146x; 1.0146x over previous
#include <cuda_runtime.h>
#include <cstdint>

// ---------------- problem constants ----------------
#define NPOS   8192          // 64 x 128 spatial positions (x1|x2 concat)
#define NCH    64
#define KC     8
#define QT     128           // queries per attn CTA
#define KVC    32            // kv chunk length per pipeline stage
#define ATT_SCALE 0.35355339059327373f   // 8^-0.5

// ---------------- scratch (device globals; no allocations) ----------------
__device__ float g_Q[4 * KC * NPOS];        // [stage][k][blocked-pos]
__device__ float g_K[4 * KC * NPOS];
__device__ float g_V[4 * NCH * NPOS];       // [stage][c][blocked-pos]
__device__ float g_ctx[4 * NCH * NPOS];     // context, blocked layout
__device__ float g_pacc0[16 * NCH * NPOS];  // stage-0 split partial acc
__device__ float g_pacc1[4 * NCH * NPOS];   // stage-1 split partial acc
__device__ float g_pl0[16 * NPOS];          // stage-0 split partial l
__device__ float g_pl1[4 * NPOS];           // stage-1 split partial l

// ---------------- packed f32x2 helpers ----------------
typedef unsigned long long u64;

__device__ __forceinline__ u64 pack2(float lo, float hi) {
    u64 r;
    asm("mov.b64 %0, {%1, %2};" : "=l"(r) : "f"(lo), "f"(hi));
    return r;
}
__device__ __forceinline__ void unpack2(u64 v, float& lo, float& hi) {
    asm("mov.b64 {%0, %1}, %2;" : "=f"(lo), "=f"(hi) : "l"(v));
}
__device__ __forceinline__ u64 fma2(u64 a, u64 b, u64 c) {
    u64 d;
    asm("fma.rn.f32x2 %0, %1, %2, %3;" : "=l"(d) : "l"(a), "l"(b), "l"(c));
    return d;
}
__device__ __forceinline__ u64 mul2(u64 a, u64 b) {
    u64 d;
    asm("mul.rn.f32x2 %0, %1, %2;" : "=l"(d) : "l"(a), "l"(b));
    return d;
}

// ---------------- cp.async helpers ----------------
__device__ __forceinline__ void cpasync4(uint32_t dst, const float* src) {
    asm volatile("cp.async.ca.shared.global [%0], [%1], 4;" :: "r"(dst), "l"(src));
}
#define CP_COMMIT() asm volatile("cp.async.commit_group;" ::: "memory")
#define CP_WAIT0()  asm volatile("cp.async.wait_group 0;"  ::: "memory")

// Blocked index: stage s (scale = 2^s), flat pos (h*128 + wfull) ->
// block * Pb + p, matching the reference's to_blocks() permutation.
__device__ __forceinline__ int blocked_idx(int s, int pos) {
    int h    = pos >> 7;
    int wf   = pos & 127;
    int half = wf >> 6;
    int w    = wf & 63;
    int l2hl = 6 - s;                 // log2(block edge)
    int msk  = (1 << l2hl) - 1;
    int bi = h >> l2hl, r = h & msk;
    int bj = w >> l2hl, c = w & msk;
    int block = (bi << s) + bj;
    int p  = (((r << l2hl) + c) << 1) + half;
    int Pb = 1 << (2 * l2hl + 1);     // hl*wl*2
    return block * Pb + p;
}

// ================= kernel 1: QKV projections (BN folded), blocked layout ===
__global__ void __launch_bounds__(256) qkv_kernel(
    const float* __restrict__ x1, const float* __restrict__ x2,
    const float* __restrict__ Wq, const float* __restrict__ bq,
    const float* __restrict__ gq, const float* __restrict__ betq,
    const float* __restrict__ Wk, const float* __restrict__ bk,
    const float* __restrict__ gk, const float* __restrict__ betk,
    const float* __restrict__ Wv, const float* __restrict__ bv)
{
    __shared__ float w_s[80 * 64];   // 8 q + 8 k + 64 v effective rows
    __shared__ float b_s[80];
    __shared__ float xs[64 * 64];    // [c][p]

    const int s   = blockIdx.y;      // stage (scale = 2^s)
    const int til = blockIdx.x;      // 0..127 position tiles of 64
    const int tid = threadIdx.x;

    for (int i = tid; i < 80 * 64; i += 256) {
        int r = i >> 6, c = i & 63;
        float w;
        if (r < 8)       w = gq[s * 8 + r] * Wq[(s * 8 + r) * 64 + c];
        else if (r < 16) w = gk[s * 8 + (r - 8)] * Wk[(s * 8 + (r - 8)) * 64 + c];
        else             w = Wv[(s * 64 + (r - 16)) * 64 + c];
        w_s[i] = w;
    }
    if (tid < 80) {
        int r = tid;
        float b;
        if (r < 8)       b = gq[s * 8 + r] * bq[s * 8 + r] + betq[s * 8 + r];
        else if (r < 16) b = gk[s * 8 + (r - 8)] * bk[s * 8 + (r - 8)] + betk[s * 8 + (r - 8)];
        else             b = bv[s * 64 + (r - 16)];
        b_s[r] = b;
    }
    const int pos0 = til * 64;
    for (int i = tid; i < 64 * 64; i += 256) {
        int c = i >> 6, p = i & 63;
        int pos = pos0 + p;
        int h = pos >> 7, wf = pos & 127;
        xs[c * 64 + p] = (wf < 64) ? x1[c * 4096 + h * 64 + wf]
                                   : x2[c * 4096 + h * 64 + (wf - 64)];
    }
    __syncthreads();

    const int p = tid & 63;
    const int g = tid >> 6;          // 4 thread groups, 20 rows each
    float acc[20];
    #pragma unroll
    for (int j = 0; j < 20; j++) acc[j] = b_s[g + 4 * j];

    for (int c = 0; c < 64; c++) {
        float xv = xs[c * 64 + p];
        #pragma unroll
        for (int j = 0; j < 20; j++)
            acc[j] += w_s[(g + 4 * j) * 64 + c] * xv;
    }

    const int bidx = blocked_idx(s, pos0 + p);
    #pragma unroll
    for (int j = 0; j < 20; j++) {
        int r = g + 4 * j;
        if (r < 8)       g_Q[(s * KC + r) * NPOS + bidx] = acc[j];
        else if (r < 16) g_K[(s * KC + (r - 8)) * NPOS + bidx] = acc[j];
        else             g_V[(s * NCH + (r - 16)) * NPOS + bidx] = acc[j];
    }
}

// ================= kernel 2: block attention (two-phase GEMM form) ========
// Per CTA: 128-query tile, kv streamed in chunks of 32 (double-buffered K/V).
// Phase A: all 256 threads compute exp'd scores into Ps[32][128] (softmax
// shift 0 — exact by invariance, scores are O(0.1)); per-thread l partial.
// Phase B: register-tiled GEMM acc[4q][4cpair] += V ⊗ P (16 FMA2 : 3 LDS).

// K/V chunk fill: kv varies fastest across threads -> coalesced gmem reads.
__device__ __forceinline__ void load_kv(uint32_t ksbuf, uint32_t vsbuf,
                                        const float* __restrict__ Kb,
                                        const float* __restrict__ Vb,
                                        int c0, int tid)
{
    {   // K: 32 kv x 4 cpair x 2 par = 256 words
        int kv = tid & 31, par = (tid >> 5) & 1, cp = tid >> 6;   // cp 0..3
        cpasync4(ksbuf + (((kv << 2) + cp) << 3) + (par << 2),
                 Kb + (2 * cp + par) * NPOS + c0 + kv);
    }
    #pragma unroll
    for (int k = 0; k < 8; k++) {   // V: 32 kv x 32 cpair x 2 par = 2048 words
        int i  = tid + k * 256;
        int kv = i & 31, par = (i >> 5) & 1, cp = i >> 6;          // cp 0..31
        cpasync4(vsbuf + (((kv << 5) + cp) << 3) + (par << 2),
                 Vb + (2 * cp + par) * NPOS + c0 + kv);
    }
}

__global__ void __launch_bounds__(256, 2) attn_kernel()
{
    __shared__ __align__(16) u64   Ks[2][KVC * 4];    // [buf][kv*4 + cpair]
    __shared__ __align__(16) u64   Vs[2][KVC * 32];   // [buf][kv*32 + cpair]
    __shared__ __align__(16) float Ps[KVC][QT];       // exp'd scores
    __shared__ float Lp[2][QT];                       // l partials (kv halves)

    const int bid = blockIdx.x;
    const int tid = threadIdx.x;

    int stage, bb, q0, split, kv0, nchunks;
    if (bid < 64) {                 // stage 2: 16 blocks x 4 qtiles, kv=512
        stage = 2; bb = (bid >> 2) * 512; q0 = (bid & 3) * 128;
        split = 0; kv0 = 0; nchunks = 16;
    } else if (bid < 1088) {        // stage 0: 64 qtiles x 16 kv-splits
        int i = bid - 64; stage = 0; bb = 0;
        q0 = (i >> 4) * 128; split = i & 15; kv0 = split * 512; nchunks = 16;
    } else if (bid < 1344) {        // stage 1: 64 qtiles x 4 kv-splits
        int i = bid - 1088; stage = 1;
        int qt = i >> 2; bb = (qt >> 4) * 2048; q0 = (qt & 15) * 128;
        split = i & 3; kv0 = split * 512; nchunks = 16;
    } else {                        // stage 3: 64 blocks, kv=128 (short, last)
        int i = bid - 1344; stage = 3; bb = i * 128; q0 = 0;
        split = 0; kv0 = 0; nchunks = 4;
    }

    const float* Qp = g_Q + stage * KC * NPOS + bb;
    const float* Kb = g_K + stage * KC * NPOS + bb;
    const float* Vb = g_V + stage * NCH * NPOS + bb;

    // phase-A identity: one (query, kv-half) per thread
    const int qa   = tid & 127;
    const int half = tid >> 7;
    // phase-B identity: 4 queries x 4 cpairs per thread (warp = one cgroup)
    const int q0b = (tid & 31) * 4;
    const int cp0 = (tid >> 5) * 4;

    u64 qr[4];
    #pragma unroll
    for (int j = 0; j < 4; j++)
        qr[j] = pack2(Qp[(2 * j) * NPOS + q0 + qa] * ATT_SCALE,
                      Qp[(2 * j + 1) * NPOS + q0 + qa] * ATT_SCALE);

    u64 acc[4][4];
    #pragma unroll
    for (int a = 0; a < 4; a++)
        #pragma unroll
        for (int b = 0; b < 4; b++) acc[a][b] = 0ull;
    float lloc = 0.0f;

    const uint32_t ks0 = (uint32_t)__cvta_generic_to_shared(&Ks[0][0]);
    const uint32_t ks1 = (uint32_t)__cvta_generic_to_shared(&Ks[1][0]);
    const uint32_t vs0 = (uint32_t)__cvta_generic_to_shared(&Vs[0][0]);
    const uint32_t vs1 = (uint32_t)__cvta_generic_to_shared(&Vs[1][0]);

    load_kv(ks0, vs0, Kb, Vb, kv0, tid);       // prologue: chunk 0 -> buf 0
    CP_COMMIT();

    for (int ch = 0; ch < nchunks; ch++) {
        CP_WAIT0();
        __syncthreads();                       // KV[cur] ready; Ps/Vs[cur^1] free
        const int cur = ch & 1;
        if (ch + 1 < nchunks) {
            load_kv(cur ? ks0 : ks1, cur ? vs0 : vs1,
                    Kb, Vb, kv0 + (ch + 1) * KVC, tid);
            CP_COMMIT();
        }

        // ---- phase A: scores -> Ps ----
        const u64* Kc = Ks[cur];
        #pragma unroll
        for (int t = 0; t < 16; t++) {
            int kv = half * 16 + t;
            ulonglong2 k01 = *(const ulonglong2*)&Kc[kv * 4];
            ulonglong2 k23 = *(const ulonglong2*)&Kc[kv * 4 + 2];
            u64 d = mul2(qr[0], k01.x);
            d = fma2(qr[1], k01.y, d);
            d = fma2(qr[2], k23.x, d);
            d = fma2(qr[3], k23.y, d);
            float a0, a1;
            unpack2(d, a0, a1);
            float e = __expf(a0 + a1);
            lloc += e;
            Ps[kv][qa] = e;
        }
        __syncthreads();                       // Ps ready

        // ---- phase B: acc += V ⊗ P ----
        const u64* Vc = Vs[cur];
        #pragma unroll 4
        for (int kv = 0; kv < KVC; kv++) {
            float4 p4 = *(const float4*)&Ps[kv][q0b];
            ulonglong2 v01 = *(const ulonglong2*)&Vc[(kv << 5) + cp0];
            ulonglong2 v23 = *(const ulonglong2*)&Vc[(kv << 5) + cp0 + 2];
            u64 e0 = pack2(p4.x, p4.x);
            u64 e1 = pack2(p4.y, p4.y);
            u64 e2 = pack2(p4.z, p4.z);
            u64 e3 = pack2(p4.w, p4.w);
            acc[0][0] = fma2(e0, v01.x, acc[0][0]);
            acc[0][1] = fma2(e0, v01.y, acc[0][1]);
            acc[0][2] = fma2(e0, v23.x, acc[0][2]);
            acc[0][3] = fma2(e0, v23.y, acc[0][3]);
            acc[1][0] = fma2(e1, v01.x, acc[1][0]);
            acc[1][1] = fma2(e1, v01.y, acc[1][1]);
            acc[1][2] = fma2(e1, v23.x, acc[1][2]);
            acc[1][3] = fma2(e1, v23.y, acc[1][3]);
            acc[2][0] = fma2(e2, v01.x, acc[2][0]);
            acc[2][1] = fma2(e2, v01.y, acc[2][1]);
            acc[2][2] = fma2(e2, v23.x, acc[2][2]);
            acc[2][3] = fma2(e2, v23.y, acc[2][3]);
            acc[3][0] = fma2(e3, v01.x, acc[3][0]);
            acc[3][1] = fma2(e3, v01.y, acc[3][1]);
            acc[3][2] = fma2(e3, v23.x, acc[3][2]);
            acc[3][3] = fma2(e3, v23.y, acc[3][3]);
        }
    }

    // ---- combine l halves ----
    Lp[half][qa] = lloc;
    __syncthreads();

    const bool fin = (stage >= 2);
    float linv[4];
    #pragma unroll
    for (int qi = 0; qi < 4; qi++) {
        float lq = Lp[0][q0b + qi] + Lp[1][q0b + qi];
        linv[qi] = fin ? (1.0f / lq) : 1.0f;
    }
    if (!fin && tid < 128) {
        float lq = Lp[0][tid] + Lp[1][tid];
        ((stage == 0) ? g_pl0 : g_pl1)[split * NPOS + bb + q0 + tid] = lq;
    }

    float* base = (stage == 0) ? (g_pacc0 + split * NCH * NPOS)
                : (stage == 1) ? (g_pacc1 + split * NCH * NPOS)
                :                (g_ctx + stage * NCH * NPOS);
    float* dst = base + bb + q0 + q0b;
    #pragma unroll
    for (int cp = 0; cp < 4; cp++) {
        float l0, h0, l1, h1, l2, h2, l3, h3;
        unpack2(acc[0][cp], l0, h0);
        unpack2(acc[1][cp], l1, h1);
        unpack2(acc[2][cp], l2, h2);
        unpack2(acc[3][cp], l3, h3);
        int c = 2 * (cp0 + cp);
        *(float4*)(dst + c * NPOS) =
            make_float4(l0 * linv[0], l1 * linv[1], l2 * linv[2], l3 * linv[3]);
        *(float4*)(dst + (c + 1) * NPOS) =
            make_float4(h0 * linv[0], h1 * linv[1], h2 * linv[2], h3 * linv[3]);
    }
}

// ================= kernel 3: split merge (stage0: 16 splits, stage1: 4) ====
// 128 CTAs x 256 threads: each thread merges 8 channels of one q4-group.
__global__ void __launch_bounds__(256) merge_kernel()
{
    int t = blockIdx.x * 256 + threadIdx.x;   // 0..32767
    int r  = t & 16383;
    int q4 = (r >> 3) * 4;                    // 2048 q-groups per stage
    int cg = (r & 7) * 8;                     // 8-channel group base
    if (t < 16384) {                          // stage 0: 16 splits
        float4 d = make_float4(0.f, 0.f, 0.f, 0.f);
        #pragma unroll
        for (int i = 0; i < 16; i++) {
            float4 l = *(const float4*)(g_pl0 + i * NPOS + q4);
            d.x += l.x; d.y += l.y; d.z += l.z; d.w += l.w;
        }
        float4 inv = make_float4(1.f / d.x, 1.f / d.y, 1.f / d.z, 1.f / d.w);
        #pragma unroll 2
        for (int cc = 0; cc < 8; cc++) {
            int c = cg + cc;
            float4 v = make_float4(0.f, 0.f, 0.f, 0.f);
            #pragma unroll
            for (int i = 0; i < 16; i++) {
                float4 a = *(const float4*)(g_pacc0 + (i * NCH + c) * NPOS + q4);
                v.x += a.x; v.y += a.y; v.z += a.z; v.w += a.w;
            }
            v.x *= inv.x; v.y *= inv.y; v.z *= inv.z; v.w *= inv.w;
            *(float4*)(g_ctx + c * NPOS + q4) = v;
        }
    } else {                                  // stage 1: 4 splits
        float4 d = make_float4(0.f, 0.f, 0.f, 0.f);
        #pragma unroll
        for (int i = 0; i < 4; i++) {
            float4 l = *(const float4*)(g_pl1 + i * NPOS + q4);
            d.x += l.x; d.y += l.y; d.z += l.z; d.w += l.w;
        }
        float4 inv = make_float4(1.f / d.x, 1.f / d.y, 1.f / d.z, 1.f / d.w);
        #pragma unroll 2
        for (int cc = 0; cc < 8; cc++) {
            int c = cg + cc;
            float4 v = make_float4(0.f, 0.f, 0.f, 0.f);
            #pragma unroll
            for (int i = 0; i < 4; i++) {
                float4 a = *(const float4*)(g_pacc1 + (i * NCH + c) * NPOS + q4);
                v.x += a.x; v.y += a.y; v.z += a.z; v.w += a.w;
            }
            v.x *= inv.x; v.y *= inv.y; v.z *= inv.z; v.w *= inv.w;
            *(float4*)(g_ctx + NCH * NPOS + c * NPOS + q4) = v;
        }
    }
}

// ================= kernel 4: final 1x1 conv (smem-tiled; unchanged) ========
__global__ void __launch_bounds__(256) final_kernel(
    const float* __restrict__ Wo, float* __restrict__ out)
{
    __shared__ __align__(16) float ctx_s[64 * 128];        // [d][wf] 32KB
    __shared__ __align__(16) float wo_s[16 * 65 * 2];      // [op][dd] u64, pad 65

    const int tid = threadIdx.x;
    const int h   = blockIdx.x;          // 0..63
    const int oh  = blockIdx.y;          // 0..1

    const int posq = tid >> 3;           // 0..31 -> 4 wf each
    const int och  = tid & 7;            // 0..7  -> 4 o each
    const int wf0  = posq * 4;

    u64 acc[4][2];
    #pragma unroll
    for (int p = 0; p < 4; p++) { acc[p][0] = 0ull; acc[p][1] = 0ull; }

    const int lwf = tid & 127;           // loop-invariant wf for tile fill
    const int ldd0 = tid >> 7;           // 0 or 1

    #pragma unroll
    for (int s = 0; s < 4; s++) {
        const float* cbase = g_ctx + s * NCH * NPOS + blocked_idx(s, h * 128 + lwf);
        #pragma unroll
        for (int k = 0; k < 32; k++) {
            int dd = ldd0 + 2 * k;
            ctx_s[dd * 128 + lwf] = cbase[dd * NPOS];
        }
        for (int i = tid; i < 2048; i += 256) {
            int op = i >> 7, rem = i & 127;
            int dd = rem >> 1, par = rem & 1;
            int o = oh * 32 + op * 2 + par;
            wo_s[op * 130 + dd * 2 + par] = Wo[o * 256 + s * 64 + dd];
        }
        __syncthreads();

        const u64* wo2 = (const u64*)wo_s;
        const int op0 = och * 2;
        #pragma unroll 8
        for (int dd = 0; dd < 64; dd++) {
            float4 cv = *(const float4*)(ctx_s + dd * 128 + wf0);
            u64 w0 = wo2[op0 * 65 + dd];
            u64 w1 = wo2[(op0 + 1) * 65 + dd];
            u64 c0 = pack2(cv.x, cv.x);
            u64 c1 = pack2(cv.y, cv.y);
            u64 c2 = pack2(cv.z, cv.z);
            u64 c3 = pack2(cv.w, cv.w);
            acc[0][0] = fma2(c0, w0, acc[0][0]);  acc[0][1] = fma2(c0, w1, acc[0][1]);
            acc[1][0] = fma2(c1, w0, acc[1][0]);  acc[1][1] = fma2(c1, w1, acc[1][1]);
            acc[2][0] = fma2(c2, w0, acc[2][0]);  acc[2][1] = fma2(c2, w1, acc[2][1]);
            acc[3][0] = fma2(c3, w0, acc[3][0]);  acc[3][1] = fma2(c3, w1, acc[3][1]);
        }
        __syncthreads();
    }

    const int halfimg = wf0 >> 6;
    const int w0i = wf0 & 63;
    float* ob = out + halfimg * 262144 + h * 64 + w0i;
    float vals[4][4];
    #pragma unroll
    for (int p = 0; p < 4; p++) {
        unpack2(acc[p][0], vals[p][0], vals[p][1]);
        unpack2(acc[p][1], vals[p][2], vals[p][3]);
    }
    #pragma unroll
    for (int j = 0; j < 4; j++) {
        int o = oh * 32 + och * 4 + j;
        float4 v = make_float4(vals[0][j], vals[1][j], vals[2][j], vals[3][j]);
        *(float4*)(ob + o * 4096) = v;
    }
}

// ================= launch ==================================================
extern "C" void kernel_launch(void* const* d_in, const int* in_sizes, int n_in,
                              void* d_out, int out_size)
{
    const float* x1   = (const float*)d_in[0];
    const float* x2   = (const float*)d_in[1];
    const float* Wq   = (const float*)d_in[2];
    const float* bq   = (const float*)d_in[3];
    const float* gq   = (const float*)d_in[4];
    const float* betq = (const float*)d_in[5];
    const float* Wk   = (const float*)d_in[6];
    const float* bk   = (const float*)d_in[7];
    const float* gk   = (const float*)d_in[8];
    const float* betk = (const float*)d_in[9];
    const float* Wv   = (const float*)d_in[10];
    const float* bv   = (const float*)d_in[11];
    const float* Wo   = (const float*)d_in[12];
    float* out = (float*)d_out;

    qkv_kernel<<<dim3(128, 4), 256>>>(x1, x2, Wq, bq, gq, betq,
                                      Wk, bk, gk, betk, Wv, bv);
    attn_kernel<<<1408, 256>>>();
    merge_kernel<<<128, 256>>>();
    final_kernel<<<dim3(64, 2), 256>>>(Wo, out);
}